// round 3
// baseline (speedup 1.0000x reference)
#include <cuda_runtime.h>
#include <math.h>

typedef unsigned long long ull;

#define PITCH   132      // smem row pitch (floats): (4r+k) banks -> conflict-free LDS.128
#define TPITCH  260      // pitch for 256-wide MLP hidden tile (260 % 32 == 4 -> same property)
#define THREADS 512

// ---------------------------------------------------------------------------
// packed f32x2 helpers (sm_103a)
// ---------------------------------------------------------------------------
__device__ __forceinline__ ull dup2(float x){
    ull r; asm("mov.b64 %0, {%1, %1};" : "=l"(r) : "f"(x)); return r;
}
__device__ __forceinline__ void fma2(ull &d, ull a, ull b){
    asm("fma.rn.f32x2 %0, %1, %2, %0;" : "+l"(d) : "l"(a), "l"(b));
}
__device__ __forceinline__ ull mul2(ull a, ull b){
    ull d; asm("mul.rn.f32x2 %0, %1, %2;" : "=l"(d) : "l"(a), "l"(b)); return d;
}
__device__ __forceinline__ ull add2(ull a, ull b){
    ull d; asm("add.rn.f32x2 %0, %1, %2;" : "=l"(d) : "l"(a), "l"(b)); return d;
}
__device__ __forceinline__ float2 unpack2(ull v){
    float2 f; asm("mov.b64 {%0, %1}, %2;" : "=f"(f.x), "=f"(f.y) : "l"(v)); return f;
}

// ---------------------------------------------------------------------------
// k-interleaved warp GEMM.
//   Warp covers 64 rows x TN cols over k in [kbase, kbase+KDW).
//   Lane = (rl, kh): rl = lane&15 row slot, kh = lane>>4 selects 4-k subgroup
//   within each 8-k round. Thread accumulates rows {rl, rl+16, rl+32, rl+48}.
//   Caller must combine halves (shfl_xor 16) afterwards.
// ---------------------------------------------------------------------------
template<int KDW, int TN>
__device__ __forceinline__ void gemm_ks(const float* __restrict__ As, int apitch,
                                        const float* __restrict__ W, int wpitch,
                                        int c0, int kbase, int rl, int kh,
                                        ull (&acc)[4][TN/2])
{
    static_assert(TN % 4 == 0 && KDW % 8 == 0, "");
#pragma unroll
    for (int i = 0; i < 4; i++)
#pragma unroll
        for (int p = 0; p < TN/2; p++) acc[i][p] = 0ull;

    const float* a0 = As + rl * apitch + kbase + 4 * kh;
    const float* w0 = W + (kbase + 4 * kh) * wpitch + c0;

#pragma unroll 2
    for (int r = 0; r < KDW/8; r++){
        float A[4][4];
#pragma unroll
        for (int i = 0; i < 4; i++){
            float4 av = *(const float4*)(a0 + i * 16 * apitch + r * 8);
            A[i][0] = av.x; A[i][1] = av.y; A[i][2] = av.z; A[i][3] = av.w;
        }
        const float* wr = w0 + r * 8 * wpitch;
#pragma unroll
        for (int j = 0; j < 4; j++){
            ull wv[TN/4][2];
#pragma unroll
            for (int p = 0; p < TN/4; p++){
                ulonglong2 t = *(const ulonglong2*)(wr + j * wpitch + 4 * p);
                wv[p][0] = t.x; wv[p][1] = t.y;
            }
#pragma unroll
            for (int i = 0; i < 4; i++){
                ull d = dup2(A[i][j]);
#pragma unroll
                for (int p = 0; p < TN/4; p++){
                    fma2(acc[i][2*p],   d, wv[p][0]);
                    fma2(acc[i][2*p+1], d, wv[p][1]);
                }
            }
        }
    }
}

// merge the two 4-k half-sums held by lane and lane^16
template<int NP>
__device__ __forceinline__ void combine_halves(ull (&acc)[4][NP]){
#pragma unroll
    for (int i = 0; i < 4; i++)
#pragma unroll
        for (int p = 0; p < NP; p++){
            ull o = __shfl_xor_sync(0xffffffffu, acc[i][p], 16);
            acc[i][p] = add2(acc[i][p], o);
        }
}

// extract TN floats from one acc row
template<int NP>
__device__ __forceinline__ void unpack_row(const ull (&a)[NP], float* r){
#pragma unroll
    for (int p = 0; p < NP; p++){
        float2 f = unpack2(a[p]);
        r[2*p] = f.x; r[2*p+1] = f.y;
    }
}

// ---------------------------------------------------------------------------
// LayerNorm over 128 cols: 8 threads per row, shfl reduction
// ---------------------------------------------------------------------------
__device__ __forceinline__ void layernorm(const float* __restrict__ Xs, float* __restrict__ Ns,
                                          const float* __restrict__ g, const float* __restrict__ b,
                                          int tid)
{
    const int row = tid >> 3, sub = tid & 7;
    const float* xr = Xs + row * PITCH;
    float s = 0.f, s2 = 0.f;
#pragma unroll
    for (int i = 0; i < 16; i++){
        float v = xr[sub + i * 8];
        s += v; s2 = fmaf(v, v, s2);
    }
#pragma unroll
    for (int o = 4; o; o >>= 1){
        s  += __shfl_xor_sync(0xffffffffu, s,  o);
        s2 += __shfl_xor_sync(0xffffffffu, s2, o);
    }
    float mu  = s  * (1.f / 128.f);
    float var = s2 * (1.f / 128.f) - mu * mu;
    float rs  = rsqrtf(var + 1e-5f);
    float* nr = Ns + row * PITCH;
#pragma unroll
    for (int i = 0; i < 16; i++){
        int c = sub + i * 8;
        nr[c] = (xr[c] - mu) * rs * g[c] + b[c];
    }
}

// ---------------------------------------------------------------------------
// Windowed attention: warp w -> head w/2, query row (w&1)*32 + lane.
// Online softmax, packed f32x2, LDS.128 (ulonglong2) k/v reads.
// ---------------------------------------------------------------------------
__device__ __forceinline__ void attention_phase(float* Qs, const float* Ks, const float* Vs, int tid)
{
    const int w    = tid >> 5;
    const int lane = tid & 31;
    const int h    = w >> 1;
    const int qi   = ((w & 1) << 5) | lane;
    const int co   = h * 16;

    const ulonglong2* qp = (const ulonglong2*)(Qs + qi * PITCH + co);
    ull q[8];
#pragma unroll
    for (int i = 0; i < 4; i++){ ulonglong2 t = qp[i]; q[2*i] = t.x; q[2*i+1] = t.y; }

    ull o[8];
#pragma unroll
    for (int i = 0; i < 8; i++) o[i] = 0ull;
    float m = -1e30f, l = 0.f;

    for (int j = 0; j < 64; j++){
        const ulonglong2* kp = (const ulonglong2*)(Ks + j * PITCH + co);
        ull accd = 0ull;
#pragma unroll
        for (int i = 0; i < 4; i++){
            ulonglong2 t = kp[i];
            fma2(accd, q[2*i],   t.x);
            fma2(accd, q[2*i+1], t.y);
        }
        float2 df = unpack2(accd);
        float s = (df.x + df.y) * 0.25f;              // HD^-0.5

        float mn   = fmaxf(m, s);
        float corr = __expf(m - mn);
        float pz   = __expf(s - mn);
        l = fmaf(l, corr, pz);
        m = mn;

        ull cd = dup2(corr);
        ull pd = dup2(pz);
        const ulonglong2* vp = (const ulonglong2*)(Vs + j * PITCH + co);
#pragma unroll
        for (int i = 0; i < 4; i++){
            ulonglong2 t = vp[i];
            ull t0 = mul2(pd, t.x); fma2(t0, o[2*i],   cd); o[2*i]   = t0;
            ull t1 = mul2(pd, t.y); fma2(t1, o[2*i+1], cd); o[2*i+1] = t1;
        }
    }
    ull inv = dup2(1.0f / l);
    ull* orow = (ull*)(Qs + qi * PITCH + co);
#pragma unroll
    for (int i = 0; i < 8; i++) orow[i] = mul2(o[i], inv);
}

// ---------------------------------------------------------------------------
// Fused transformer block: one CTA = one 64-token window.
// ---------------------------------------------------------------------------
extern __shared__ float smbuf[];

__global__ void __launch_bounds__(THREADS, 1)
fused_block_kernel(const float* __restrict__ feats,
                   const float* __restrict__ w_pre,  const float* __restrict__ b_pre,
                   const float* __restrict__ g1,     const float* __restrict__ b1,
                   const float* __restrict__ w_qkv,  const float* __restrict__ b_qkv,
                   const float* __restrict__ w_proj, const float* __restrict__ b_proj,
                   const float* __restrict__ g2,     const float* __restrict__ b2,
                   const float* __restrict__ w_m1,   const float* __restrict__ b_m1,
                   const float* __restrict__ w_m2,   const float* __restrict__ b_m2,
                   const float* __restrict__ w_post, const float* __restrict__ b_post,
                   float* __restrict__ out)
{
    float* Xs = smbuf;                  // residual stream x2  [64][132]
    float* Ns = smbuf + 64 * PITCH;     // LN output / feats staging
    float* Qs = smbuf + 2 * 64 * PITCH; // q -> attention output
    float* Ks = smbuf + 3 * 64 * PITCH; // k -> MLP hidden (TPITCH spans Ks+Vs)
    float* Vs = smbuf + 4 * 64 * PITCH; // v
    float* Ss = smbuf + 5 * 64 * PITCH; // k-split partial scratch
    float* Ts = Ks;

    const int tid  = threadIdx.x;
    const int warp = tid >> 5;
    const int lane = tid & 31;
    const int rl   = lane & 15;
    const int kh   = lane >> 4;
    const int cw   = warp & 7;          // column-warp id for k-split gemms
    const int g    = warp >> 3;         // k-group for k-split gemms
    const int row0 = rl + kh * 32;      // epilogue rows: row0, row0+16
    const int i0   = kh * 2;            // matching acc row indices
    const size_t tok0 = (size_t)blockIdx.x * 64;

    // stage feats tile [64][64] into Ns cols 0..63
    for (int i = tid; i < 64 * 16; i += THREADS){
        int t = i >> 4, c4 = i & 15;
        float4 v = ((const float4*)(feats + (tok0 + t) * 64))[c4];
        *(float4*)(Ns + t * PITCH + c4 * 4) = v;
    }
    __syncthreads();

    // ---- pre: x2 = feats @ w_pre + b_pre  (K=64, warp-k-split) ----
    {
        int c0 = cw * 16;
        ull acc[4][8];
        gemm_ks<32, 16>(Ns, PITCH, w_pre, 128, c0, 32 * g, rl, kh, acc);
        combine_halves<8>(acc);
        if (g == 1){
#pragma unroll
            for (int m = 0; m < 2; m++){
                float r[16]; unpack_row<8>(acc[i0 + m], r);
                float* d = Ss + (row0 + m * 16) * PITCH + c0;
#pragma unroll
                for (int q4 = 0; q4 < 4; q4++)
                    *(float4*)(d + 4*q4) = make_float4(r[4*q4], r[4*q4+1], r[4*q4+2], r[4*q4+3]);
            }
        }
        __syncthreads();
        if (g == 0){
#pragma unroll
            for (int m = 0; m < 2; m++){
                float r[16]; unpack_row<8>(acc[i0 + m], r);
                int rw = row0 + m * 16;
                const float* p = Ss + rw * PITCH + c0;
                float* d = Xs + rw * PITCH + c0;
#pragma unroll
                for (int c = 0; c < 16; c++)
                    d[c] = r[c] + p[c] + b_pre[c0 + c];
            }
        }
        __syncthreads();
    }

    layernorm(Xs, Ns, g1, b1, tid);
    __syncthreads();

    // ---- q,k fused: 256 cols of w_qkv, full K=128, 16 warps ----
    {
        int c0 = warp * 16;
        ull acc[4][8];
        gemm_ks<128, 16>(Ns, PITCH, w_qkv, 384, c0, 0, rl, kh, acc);
        combine_halves<8>(acc);
        float* dst = (warp < 8) ? (Qs + c0) : (Ks + c0 - 128);
#pragma unroll
        for (int m = 0; m < 2; m++){
            float r[16]; unpack_row<8>(acc[i0 + m], r);
            float* d = dst + (row0 + m * 16) * PITCH;
#pragma unroll
            for (int c = 0; c < 16; c++)
                d[c] = r[c] + b_qkv[c0 + c];
        }
    }

    // ---- v: cols 256..383, warp-k-split ----
    {
        int c0 = 256 + cw * 16;
        ull acc[4][8];
        gemm_ks<64, 16>(Ns, PITCH, w_qkv, 384, c0, 64 * g, rl, kh, acc);
        combine_halves<8>(acc);
        if (g == 1){
#pragma unroll
            for (int m = 0; m < 2; m++){
                float r[16]; unpack_row<8>(acc[i0 + m], r);
                float* d = Ss + (row0 + m * 16) * PITCH + cw * 16;
#pragma unroll
                for (int q4 = 0; q4 < 4; q4++)
                    *(float4*)(d + 4*q4) = make_float4(r[4*q4], r[4*q4+1], r[4*q4+2], r[4*q4+3]);
            }
        }
        __syncthreads();   // also fences Qs/Ks writes above
        if (g == 0){
#pragma unroll
            for (int m = 0; m < 2; m++){
                float r[16]; unpack_row<8>(acc[i0 + m], r);
                int rw = row0 + m * 16;
                const float* p = Ss + rw * PITCH + cw * 16;
                float* d = Vs + rw * PITCH + cw * 16;
#pragma unroll
                for (int c = 0; c < 16; c++)
                    d[c] = r[c] + p[c] + b_qkv[c0 + c];
            }
        }
        __syncthreads();
    }

    attention_phase(Qs, Ks, Vs, tid);
    __syncthreads();

    // ---- proj + residual: x2 += o @ w_proj + b_proj  (warp-k-split) ----
    {
        int c0 = cw * 16;
        ull acc[4][8];
        gemm_ks<64, 16>(Qs, PITCH, w_proj, 128, c0, 64 * g, rl, kh, acc);
        combine_halves<8>(acc);
        if (g == 1){
#pragma unroll
            for (int m = 0; m < 2; m++){
                float r[16]; unpack_row<8>(acc[i0 + m], r);
                float* d = Ss + (row0 + m * 16) * PITCH + c0;
#pragma unroll
                for (int q4 = 0; q4 < 4; q4++)
                    *(float4*)(d + 4*q4) = make_float4(r[4*q4], r[4*q4+1], r[4*q4+2], r[4*q4+3]);
            }
        }
        __syncthreads();
        if (g == 0){
#pragma unroll
            for (int m = 0; m < 2; m++){
                float r[16]; unpack_row<8>(acc[i0 + m], r);
                int rw = row0 + m * 16;
                const float* p = Ss + rw * PITCH + c0;
                float* d = Xs + rw * PITCH + c0;
#pragma unroll
                for (int c = 0; c < 16; c++)
                    d[c] += r[c] + p[c] + b_proj[c0 + c];
            }
        }
        __syncthreads();
    }

    layernorm(Xs, Ns, g2, b2, tid);
    __syncthreads();

    // ---- mlp1: t = gelu(n2 @ w_m1 + b_m1)  (256 cols, 16 warps, full K) ----
    {
        int c0 = warp * 16;
        ull acc[4][8];
        gemm_ks<128, 16>(Ns, PITCH, w_m1, 256, c0, 0, rl, kh, acc);
        combine_halves<8>(acc);
#pragma unroll
        for (int m = 0; m < 2; m++){
            float r[16]; unpack_row<8>(acc[i0 + m], r);
            float* d = Ts + (row0 + m * 16) * TPITCH + c0;
#pragma unroll
            for (int c = 0; c < 16; c++){
                float x = r[c] + b_m1[c0 + c];
                d[c] = 0.5f * x * (1.0f + erff(x * 0.70710678118654752f));
            }
        }
        __syncthreads();
    }

    // ---- mlp2 + residual: x2 += t @ w_m2 + b_m2  (K=256, warp-k-split) ----
    {
        int c0 = cw * 16;
        ull acc[4][8];
        gemm_ks<128, 16>(Ts, TPITCH, w_m2, 128, c0, 128 * g, rl, kh, acc);
        combine_halves<8>(acc);
        if (g == 1){
#pragma unroll
            for (int m = 0; m < 2; m++){
                float r[16]; unpack_row<8>(acc[i0 + m], r);
                float* d = Ss + (row0 + m * 16) * PITCH + c0;
#pragma unroll
                for (int q4 = 0; q4 < 4; q4++)
                    *(float4*)(d + 4*q4) = make_float4(r[4*q4], r[4*q4+1], r[4*q4+2], r[4*q4+3]);
            }
        }
        __syncthreads();
        if (g == 0){
#pragma unroll
            for (int m = 0; m < 2; m++){
                float r[16]; unpack_row<8>(acc[i0 + m], r);
                int rw = row0 + m * 16;
                const float* p = Ss + rw * PITCH + c0;
                float* d = Xs + rw * PITCH + c0;
#pragma unroll
                for (int c = 0; c < 16; c++)
                    d[c] += r[c] + p[c] + b_m2[c0 + c];
            }
        }
        __syncthreads();
    }

    // ---- post: out = x2 @ w_post + b_post  (64 cols, TN=4, full K) ----
    {
        int c0 = warp * 4;
        ull acc[4][2];
        gemm_ks<128, 4>(Xs, PITCH, w_post, 64, c0, 0, rl, kh, acc);
        combine_halves<2>(acc);
#pragma unroll
        for (int m = 0; m < 2; m++){
            float r[4]; unpack_row<2>(acc[i0 + m], r);
            int rw = row0 + m * 16;
            float4 v = make_float4(r[0] + b_post[c0],
                                   r[1] + b_post[c0 + 1],
                                   r[2] + b_post[c0 + 2],
                                   r[3] + b_post[c0 + 3]);
            *(float4*)(out + (tok0 + rw) * 64 + c0) = v;
        }
    }
}

extern "C" void kernel_launch(void* const* d_in, const int* in_sizes, int n_in,
                              void* d_out, int out_size)
{
    const float* feats  = (const float*)d_in[0];
    const float* w_pre  = (const float*)d_in[1];
    const float* b_pre  = (const float*)d_in[2];
    const float* g1     = (const float*)d_in[3];
    const float* b1     = (const float*)d_in[4];
    const float* w_qkv  = (const float*)d_in[5];
    const float* b_qkv  = (const float*)d_in[6];
    const float* w_proj = (const float*)d_in[7];
    const float* b_proj = (const float*)d_in[8];
    const float* g2     = (const float*)d_in[9];
    const float* b2     = (const float*)d_in[10];
    const float* w_m1   = (const float*)d_in[11];
    const float* b_m1   = (const float*)d_in[12];
    const float* w_m2   = (const float*)d_in[13];
    const float* b_m2   = (const float*)d_in[14];
    const float* w_post = (const float*)d_in[15];
    const float* b_post = (const float*)d_in[16];
    float* out = (float*)d_out;

    const int ntok    = in_sizes[0] / 64;   // C = 64
    const int nblocks = ntok / 64;          // PS = 64 tokens per window
    const size_t smem = (size_t)6 * 64 * PITCH * sizeof(float);   // 202752 B

    cudaFuncSetAttribute(fused_block_kernel,
                         cudaFuncAttributeMaxDynamicSharedMemorySize, (int)smem);

    fused_block_kernel<<<nblocks, THREADS, smem>>>(feats, w_pre, b_pre, g1, b1,
                                                   w_qkv, b_qkv, w_proj, b_proj,
                                                   g2, b2, w_m1, b_m1, w_m2, b_m2,
                                                   w_post, b_post, out);
}

// round 4
// speedup vs baseline: 3.0545x; 3.0545x over previous
#include <cuda_runtime.h>
#include <math.h>

typedef unsigned int uint;

#define PITCH   132      // activation smem pitch: bank = 4*row + k -> conflict-free frags
#define TPITCH  260      // MLP hidden tile pitch (260 % 32 == 4 -> same property)
#define WPITCH  136      // staged weight pitch: bank = 8*k + n -> conflict-free B frags
#define THREADS 512

// ---------------------------------------------------------------------------
// tf32 helpers
// ---------------------------------------------------------------------------
__device__ __forceinline__ uint tf32r(float f){
    uint u; asm("cvt.rna.tf32.f32 %0, %1;" : "=r"(u) : "f"(f)); return u;
}
__device__ __forceinline__ float tf32f(float f){ return __uint_as_float(tf32r(f)); }

// m16n8k8 tf32 MMA, fp32 accumulate (canonical fragment layout)
__device__ __forceinline__ void mma8(float (&c)[4],
                                     uint a0, uint a1, uint a2, uint a3,
                                     uint b0, uint b1){
    asm("mma.sync.aligned.m16n8k8.row.col.f32.tf32.tf32.f32 "
        "{%0,%1,%2,%3}, {%4,%5,%6,%7}, {%8,%9}, {%0,%1,%2,%3};"
        : "+f"(c[0]), "+f"(c[1]), "+f"(c[2]), "+f"(c[3])
        : "r"(a0), "r"(a1), "r"(a2), "r"(a3), "r"(b0), "r"(b1));
}

// ---------------------------------------------------------------------------
// Stage a 64-row x NCH-col weight chunk into smem (tf32-rounded), coalesced.
// ---------------------------------------------------------------------------
template<int NCH>
__device__ __forceinline__ void stage_w(const float* __restrict__ W, int wpitch,
                                        int k0, int cc0, float* Ws, int tid){
    constexpr int C4 = NCH / 4;
#pragma unroll
    for (int idx = tid; idx < 64 * C4; idx += THREADS){
        int row = idx / C4, c4 = idx % C4;
        float4 v = *(const float4*)(W + (size_t)(k0 + row) * wpitch + cc0 + 4 * c4);
        uint4 o = make_uint4(tf32r(v.x), tf32r(v.y), tf32r(v.z), tf32r(v.w));
        *(uint4*)((uint*)Ws + row * WPITCH + 4 * c4) = o;
    }
}

// ---------------------------------------------------------------------------
// One GEMM col-chunk: C[64][NCH] += A[64][KTOT] @ W[KTOT][cc0..cc0+NCH)
// Warp (mg, ng) computes rows mg*16..+15, cols ng*NT*8..+NT*8-1 (within chunk).
// Weights staged per 64-k chunk; A from smem (tf32-rounded unless CVT_A).
// ---------------------------------------------------------------------------
template<int KTOT, int NT, int NCH, bool CVT_A>
__device__ __forceinline__ void gemm_chunk(const float* __restrict__ As, int apitch,
                                           const float* __restrict__ W, int wpitch, int cc0,
                                           float* Ws, int tid, float (&c)[NT][4]){
    const int warp = tid >> 5, lane = tid & 31;
    const int g = lane >> 2, t = lane & 3;
    const int mg = warp >> 2, ng = warp & 3;
    const int wcol0 = ng * NT * 8;

#pragma unroll
    for (int nt = 0; nt < NT; nt++)
#pragma unroll
        for (int i = 0; i < 4; i++) c[nt][i] = 0.f;

    const float* a0p = As + (mg * 16 + g) * apitch + t;
    const float* a1p = a0p + 8 * apitch;

    for (int k0 = 0; k0 < KTOT; k0 += 64){
        __syncthreads();                       // also fences prior epilogue/As writes
        stage_w<NCH>(W, wpitch, k0, cc0, Ws, tid);
        __syncthreads();
#pragma unroll
        for (int kk = 0; kk < 64; kk += 8){
            float f0 = a0p[k0 + kk],     f1 = a1p[k0 + kk];
            float f2 = a0p[k0 + kk + 4], f3 = a1p[k0 + kk + 4];
            uint a0, a1, a2, a3;
            if (CVT_A){ a0 = tf32r(f0); a1 = tf32r(f1); a2 = tf32r(f2); a3 = tf32r(f3); }
            else      { a0 = __float_as_uint(f0); a1 = __float_as_uint(f1);
                        a2 = __float_as_uint(f2); a3 = __float_as_uint(f3); }
            const float* wb = Ws + (kk + t) * WPITCH + wcol0 + g;
#pragma unroll
            for (int nt = 0; nt < NT; nt++){
                uint b0 = __float_as_uint(wb[nt * 8]);
                uint b1 = __float_as_uint(wb[nt * 8 + 4 * WPITCH]);
                mma8(c[nt], a0, a1, a2, a3, b0, b1);
            }
        }
    }
}

// ---------------------------------------------------------------------------
// LayerNorm over 128 cols -> tf32-rounded output
// ---------------------------------------------------------------------------
__device__ __forceinline__ void layernorm(const float* __restrict__ Xs, float* __restrict__ Ns,
                                          const float* __restrict__ g, const float* __restrict__ b,
                                          int tid)
{
    const int row = tid >> 3, sub = tid & 7;
    const float* xr = Xs + row * PITCH;
    float s = 0.f, s2 = 0.f;
#pragma unroll
    for (int i = 0; i < 16; i++){
        float v = xr[sub + i * 8];
        s += v; s2 = fmaf(v, v, s2);
    }
#pragma unroll
    for (int o = 4; o; o >>= 1){
        s  += __shfl_xor_sync(0xffffffffu, s,  o);
        s2 += __shfl_xor_sync(0xffffffffu, s2, o);
    }
    float mu  = s  * (1.f / 128.f);
    float var = s2 * (1.f / 128.f) - mu * mu;
    float rs  = rsqrtf(var + 1e-5f);
    float* nr = Ns + row * PITCH;
#pragma unroll
    for (int i = 0; i < 16; i++){
        int c = sub + i * 8;
        nr[c] = tf32f((xr[c] - mu) * rs * g[c] + b[c]);
    }
}

// ---------------------------------------------------------------------------
// Windowed attention (fp32 FFMA path): warp w -> head w/2, row (w&1)*32+lane.
// ---------------------------------------------------------------------------
typedef unsigned long long ull;
__device__ __forceinline__ ull dup2(float x){
    ull r; asm("mov.b64 %0, {%1, %1};" : "=l"(r) : "f"(x)); return r;
}
__device__ __forceinline__ void fma2(ull &d, ull a, ull b){
    asm("fma.rn.f32x2 %0, %1, %2, %0;" : "+l"(d) : "l"(a), "l"(b));
}
__device__ __forceinline__ ull mul2(ull a, ull b){
    ull d; asm("mul.rn.f32x2 %0, %1, %2;" : "=l"(d) : "l"(a), "l"(b)); return d;
}
__device__ __forceinline__ float2 unpack2(ull v){
    float2 f; asm("mov.b64 {%0, %1}, %2;" : "=f"(f.x), "=f"(f.y) : "l"(v)); return f;
}

__device__ __forceinline__ void attention_phase(float* Qs, const float* Ks, const float* Vs, int tid)
{
    const int w    = tid >> 5;
    const int lane = tid & 31;
    const int h    = w >> 1;
    const int qi   = ((w & 1) << 5) | lane;
    const int co   = h * 16;

    const ulonglong2* qp = (const ulonglong2*)(Qs + qi * PITCH + co);
    ull q[8];
#pragma unroll
    for (int i = 0; i < 4; i++){ ulonglong2 t = qp[i]; q[2*i] = t.x; q[2*i+1] = t.y; }

    ull o[8];
#pragma unroll
    for (int i = 0; i < 8; i++) o[i] = 0ull;
    float m = -1e30f, l = 0.f;

    for (int j = 0; j < 64; j++){
        const ulonglong2* kp = (const ulonglong2*)(Ks + j * PITCH + co);
        ull accd = 0ull;
#pragma unroll
        for (int i = 0; i < 4; i++){
            ulonglong2 t = kp[i];
            fma2(accd, q[2*i],   t.x);
            fma2(accd, q[2*i+1], t.y);
        }
        float2 df = unpack2(accd);
        float s = (df.x + df.y) * 0.25f;              // HD^-0.5

        float mn   = fmaxf(m, s);
        float corr = __expf(m - mn);
        float pz   = __expf(s - mn);
        l = fmaf(l, corr, pz);
        m = mn;

        ull cd = dup2(corr);
        ull pd = dup2(pz);
        const ulonglong2* vp = (const ulonglong2*)(Vs + j * PITCH + co);
#pragma unroll
        for (int i = 0; i < 4; i++){
            ulonglong2 t = vp[i];
            ull t0 = mul2(pd, t.x); fma2(t0, o[2*i],   cd); o[2*i]   = t0;
            ull t1 = mul2(pd, t.y); fma2(t1, o[2*i+1], cd); o[2*i+1] = t1;
        }
    }
    ull inv = dup2(1.0f / l);
    ull* orow = (ull*)(Qs + qi * PITCH + co);
#pragma unroll
    for (int i = 0; i < 8; i++) orow[i] = mul2(o[i], inv);
}

// ---------------------------------------------------------------------------
// Fused transformer block: one CTA = one 64-token window, tf32 tensor GEMMs.
// ---------------------------------------------------------------------------
extern __shared__ float smbuf[];

__global__ void __launch_bounds__(THREADS, 1)
fused_block_kernel(const float* __restrict__ feats,
                   const float* __restrict__ w_pre,  const float* __restrict__ b_pre,
                   const float* __restrict__ g1,     const float* __restrict__ b1,
                   const float* __restrict__ w_qkv,  const float* __restrict__ b_qkv,
                   const float* __restrict__ w_proj, const float* __restrict__ b_proj,
                   const float* __restrict__ g2,     const float* __restrict__ b2,
                   const float* __restrict__ w_m1,   const float* __restrict__ b_m1,
                   const float* __restrict__ w_m2,   const float* __restrict__ b_m2,
                   const float* __restrict__ w_post, const float* __restrict__ b_post,
                   float* __restrict__ out)
{
    float* Xs = smbuf;                  // residual stream (fp32)     [64][132]
    float* Ns = smbuf + 64 * PITCH;     // LN out / staged feats (tf32-rounded)
    float* Qs = smbuf + 2 * 64 * PITCH; // q -> attention output o
    float* Ks = smbuf + 3 * 64 * PITCH; // k -> MLP hidden (pitch 260 spans Ks+Vs)
    float* Vs = smbuf + 4 * 64 * PITCH; // v
    float* Ws = smbuf + 5 * 64 * PITCH; // weight staging [64][136]
    float* Ts = Ks;

    const int tid  = threadIdx.x;
    const int warp = tid >> 5, lane = tid & 31;
    const int g    = lane >> 2, t = lane & 3;
    const int mg   = warp >> 2, ng = warp & 3;
    const int r0   = mg * 16 + g;
    const size_t tok0 = (size_t)blockIdx.x * 64;

    // stage feats tile [64][64] into Ns cols 0..63 (tf32-rounded)
    for (int i = tid; i < 64 * 16; i += THREADS){
        int tk = i >> 4, c4 = i & 15;
        float4 v = ((const float4*)(feats + (tok0 + tk) * 64))[c4];
        uint4 o = make_uint4(tf32r(v.x), tf32r(v.y), tf32r(v.z), tf32r(v.w));
        *(uint4*)((uint*)Ns + tk * PITCH + c4 * 4) = o;
    }
    // gemm_chunk's internal first __syncthreads orders staging vs compute

    // ---- pre: x2 = feats @ w_pre + b_pre  (K=64 -> N=128) ----
    {
        float c[4][4];
        gemm_chunk<64, 4, 128, false>(Ns, PITCH, w_pre, 128, 0, Ws, tid, c);
#pragma unroll
        for (int nt = 0; nt < 4; nt++){
            int col = ng * 32 + nt * 8 + 2 * t;
            float2 bv = *(const float2*)(b_pre + col);
            *(float2*)(Xs + r0 * PITCH + col)       = make_float2(c[nt][0] + bv.x, c[nt][1] + bv.y);
            *(float2*)(Xs + (r0 + 8) * PITCH + col) = make_float2(c[nt][2] + bv.x, c[nt][3] + bv.y);
        }
    }
    __syncthreads();
    layernorm(Xs, Ns, g1, b1, tid);

    // ---- qkv: 3 col-chunks of w_qkv (N=384), K=128 ----
    {
        float* dsts[3] = {Qs, Ks, Vs};
#pragma unroll
        for (int ch = 0; ch < 3; ch++){
            float c[4][4];
            gemm_chunk<128, 4, 128, false>(Ns, PITCH, w_qkv, 384, ch * 128, Ws, tid, c);
            float* dst = dsts[ch];
#pragma unroll
            for (int nt = 0; nt < 4; nt++){
                int col = ng * 32 + nt * 8 + 2 * t;
                float2 bv = *(const float2*)(b_qkv + ch * 128 + col);
                *(float2*)(dst + r0 * PITCH + col) =
                    make_float2(tf32f(c[nt][0] + bv.x), tf32f(c[nt][1] + bv.y));
                *(float2*)(dst + (r0 + 8) * PITCH + col) =
                    make_float2(tf32f(c[nt][2] + bv.x), tf32f(c[nt][3] + bv.y));
            }
        }
    }
    __syncthreads();

    attention_phase(Qs, Ks, Vs, tid);   // o -> Qs (fp32)

    // ---- proj + residual: x2 += o @ w_proj + b_proj ----
    {
        float c[4][4];
        gemm_chunk<128, 4, 128, true>(Qs, PITCH, w_proj, 128, 0, Ws, tid, c);
#pragma unroll
        for (int nt = 0; nt < 4; nt++){
            int col = ng * 32 + nt * 8 + 2 * t;
            float2 bv = *(const float2*)(b_proj + col);
            float2* p0 = (float2*)(Xs + r0 * PITCH + col);
            float2* p1 = (float2*)(Xs + (r0 + 8) * PITCH + col);
            float2 v0 = *p0, v1 = *p1;
            v0.x += c[nt][0] + bv.x; v0.y += c[nt][1] + bv.y;
            v1.x += c[nt][2] + bv.x; v1.y += c[nt][3] + bv.y;
            *p0 = v0; *p1 = v1;
        }
    }
    __syncthreads();
    layernorm(Xs, Ns, g2, b2, tid);

    // ---- mlp1: t = gelu(n2 @ w_m1 + b_m1)  (N=256: 2 col-chunks) ----
#pragma unroll
    for (int ch = 0; ch < 2; ch++){
        float c[4][4];
        gemm_chunk<128, 4, 128, false>(Ns, PITCH, w_m1, 256, ch * 128, Ws, tid, c);
#pragma unroll
        for (int nt = 0; nt < 4; nt++){
            int col = ng * 32 + nt * 8 + 2 * t;
            float2 bv = *(const float2*)(b_m1 + ch * 128 + col);
            float v[4] = {c[nt][0] + bv.x, c[nt][1] + bv.y,
                          c[nt][2] + bv.x, c[nt][3] + bv.y};
#pragma unroll
            for (int i = 0; i < 4; i++)
                v[i] = tf32f(0.5f * v[i] * (1.0f + erff(v[i] * 0.70710678118654752f)));
            *(float2*)(Ts + r0 * TPITCH + ch * 128 + col)       = make_float2(v[0], v[1]);
            *(float2*)(Ts + (r0 + 8) * TPITCH + ch * 128 + col) = make_float2(v[2], v[3]);
        }
    }

    // ---- mlp2 + residual: x2 += t @ w_m2 + b_m2  (K=256) ----
    {
        float c[4][4];
        gemm_chunk<256, 4, 128, false>(Ts, TPITCH, w_m2, 128, 0, Ws, tid, c);
#pragma unroll
        for (int nt = 0; nt < 4; nt++){
            int col = ng * 32 + nt * 8 + 2 * t;
            float2 bv = *(const float2*)(b_m2 + col);
            float2* p0 = (float2*)(Xs + r0 * PITCH + col);
            float2* p1 = (float2*)(Xs + (r0 + 8) * PITCH + col);
            float2 v0 = *p0, v1 = *p1;
            v0.x += c[nt][0] + bv.x; v0.y += c[nt][1] + bv.y;
            v1.x += c[nt][2] + bv.x; v1.y += c[nt][3] + bv.y;
            *p0 = v0; *p1 = v1;
        }
    }

    // ---- post: out = x2 @ w_post + b_post  (N=64, NT=2) ----
    {
        float c[2][4];
        gemm_chunk<128, 2, 64, true>(Xs, PITCH, w_post, 64, 0, Ws, tid, c);
#pragma unroll
        for (int nt = 0; nt < 2; nt++){
            int col = ng * 16 + nt * 8 + 2 * t;
            float2 bv = *(const float2*)(b_post + col);
            *(float2*)(out + (tok0 + r0) * 64 + col) =
                make_float2(c[nt][0] + bv.x, c[nt][1] + bv.y);
            *(float2*)(out + (tok0 + r0 + 8) * 64 + col) =
                make_float2(c[nt][2] + bv.x, c[nt][3] + bv.y);
        }
    }
}

extern "C" void kernel_launch(void* const* d_in, const int* in_sizes, int n_in,
                              void* d_out, int out_size)
{
    const float* feats  = (const float*)d_in[0];
    const float* w_pre  = (const float*)d_in[1];
    const float* b_pre  = (const float*)d_in[2];
    const float* g1     = (const float*)d_in[3];
    const float* b1     = (const float*)d_in[4];
    const float* w_qkv  = (const float*)d_in[5];
    const float* b_qkv  = (const float*)d_in[6];
    const float* w_proj = (const float*)d_in[7];
    const float* b_proj = (const float*)d_in[8];
    const float* g2     = (const float*)d_in[9];
    const float* b2     = (const float*)d_in[10];
    const float* w_m1   = (const float*)d_in[11];
    const float* b_m1   = (const float*)d_in[12];
    const float* w_m2   = (const float*)d_in[13];
    const float* b_m2   = (const float*)d_in[14];
    const float* w_post = (const float*)d_in[15];
    const float* b_post = (const float*)d_in[16];
    float* out = (float*)d_out;

    const int ntok    = in_sizes[0] / 64;   // C = 64
    const int nblocks = ntok / 64;          // PS = 64 tokens per window
    const size_t smem = (size_t)(5 * 64 * PITCH + 64 * WPITCH) * sizeof(float); // 203776 B

    cudaFuncSetAttribute(fused_block_kernel,
                         cudaFuncAttributeMaxDynamicSharedMemorySize, (int)smem);

    fused_block_kernel<<<nblocks, THREADS, smem>>>(feats, w_pre, b_pre, g1, b1,
                                                   w_qkv, b_qkv, w_proj, b_proj,
                                                   g2, b2, w_m1, b_m1, w_m2, b_m2,
                                                   w_post, b_post, out);
}

// round 5
// speedup vs baseline: 3.6306x; 1.1886x over previous
#include <cuda_runtime.h>
#include <math.h>

typedef unsigned int uint;

#define PITCH   132      // activation smem pitch: bank = 4*row + k -> conflict-free frags
#define TPITCH  260      // MLP hidden tile pitch (260 % 32 == 4 -> same property)
#define WPITCH  136      // staged weight pitch: bank = 8*k + n -> conflict-free B frags
#define THREADS 512

// ---------------------------------------------------------------------------
// tf32 helpers
// ---------------------------------------------------------------------------
__device__ __forceinline__ uint tf32r(float f){
    uint u; asm("cvt.rna.tf32.f32 %0, %1;" : "=r"(u) : "f"(f)); return u;
}
__device__ __forceinline__ float tf32f(float f){ return __uint_as_float(tf32r(f)); }

// m16n8k8 tf32 MMA, fp32 accumulate (canonical fragment layout)
__device__ __forceinline__ void mma8(float (&c)[4],
                                     uint a0, uint a1, uint a2, uint a3,
                                     uint b0, uint b1){
    asm("mma.sync.aligned.m16n8k8.row.col.f32.tf32.tf32.f32 "
        "{%0,%1,%2,%3}, {%4,%5,%6,%7}, {%8,%9}, {%0,%1,%2,%3};"
        : "+f"(c[0]), "+f"(c[1]), "+f"(c[2]), "+f"(c[3])
        : "r"(a0), "r"(a1), "r"(a2), "r"(a3), "r"(b0), "r"(b1));
}

// ---------------------------------------------------------------------------
// Stage a 64-row x NCH-col weight chunk into smem (tf32-rounded), coalesced.
// ---------------------------------------------------------------------------
template<int NCH>
__device__ __forceinline__ void stage_w(const float* __restrict__ W, int wpitch,
                                        int k0, int cc0, float* Ws, int tid){
    constexpr int C4 = NCH / 4;
#pragma unroll
    for (int idx = tid; idx < 64 * C4; idx += THREADS){
        int row = idx / C4, c4 = idx % C4;
        float4 v = *(const float4*)(W + (size_t)(k0 + row) * wpitch + cc0 + 4 * c4);
        uint4 o = make_uint4(tf32r(v.x), tf32r(v.y), tf32r(v.z), tf32r(v.w));
        *(uint4*)((uint*)Ws + row * WPITCH + 4 * c4) = o;
    }
}

// ---------------------------------------------------------------------------
// One GEMM col-chunk: C[64][NCH] += A[64][KTOT] @ W[KTOT][cc0..cc0+NCH)
// Warp (mg, ng) computes rows mg*16..+15, cols ng*NT*8..+NT*8-1 (within chunk).
// ---------------------------------------------------------------------------
template<int KTOT, int NT, int NCH, bool CVT_A>
__device__ __forceinline__ void gemm_chunk(const float* __restrict__ As, int apitch,
                                           const float* __restrict__ W, int wpitch, int cc0,
                                           float* Ws, int tid, float (&c)[NT][4]){
    const int warp = tid >> 5, lane = tid & 31;
    const int g = lane >> 2, t = lane & 3;
    const int mg = warp >> 2, ng = warp & 3;
    const int wcol0 = ng * NT * 8;

#pragma unroll
    for (int nt = 0; nt < NT; nt++)
#pragma unroll
        for (int i = 0; i < 4; i++) c[nt][i] = 0.f;

    const float* a0p = As + (mg * 16 + g) * apitch + t;
    const float* a1p = a0p + 8 * apitch;

    for (int k0 = 0; k0 < KTOT; k0 += 64){
        __syncthreads();                       // also fences prior epilogue/As writes
        stage_w<NCH>(W, wpitch, k0, cc0, Ws, tid);
        __syncthreads();
#pragma unroll
        for (int kk = 0; kk < 64; kk += 8){
            float f0 = a0p[k0 + kk],     f1 = a1p[k0 + kk];
            float f2 = a0p[k0 + kk + 4], f3 = a1p[k0 + kk + 4];
            uint a0, a1, a2, a3;
            if (CVT_A){ a0 = tf32r(f0); a1 = tf32r(f1); a2 = tf32r(f2); a3 = tf32r(f3); }
            else      { a0 = __float_as_uint(f0); a1 = __float_as_uint(f1);
                        a2 = __float_as_uint(f2); a3 = __float_as_uint(f3); }
            const float* wb = Ws + (kk + t) * WPITCH + wcol0 + g;
#pragma unroll
            for (int nt = 0; nt < NT; nt++){
                uint b0 = __float_as_uint(wb[nt * 8]);
                uint b1 = __float_as_uint(wb[nt * 8 + 4 * WPITCH]);
                mma8(c[nt], a0, a1, a2, a3, b0, b1);
            }
        }
    }
}

// ---------------------------------------------------------------------------
// LayerNorm over 128 cols -> tf32-rounded output
// ---------------------------------------------------------------------------
__device__ __forceinline__ void layernorm(const float* __restrict__ Xs, float* __restrict__ Ns,
                                          const float* __restrict__ g, const float* __restrict__ b,
                                          int tid)
{
    const int row = tid >> 3, sub = tid & 7;
    const float* xr = Xs + row * PITCH;
    float s = 0.f, s2 = 0.f;
#pragma unroll
    for (int i = 0; i < 16; i++){
        float v = xr[sub + i * 8];
        s += v; s2 = fmaf(v, v, s2);
    }
#pragma unroll
    for (int o = 4; o; o >>= 1){
        s  += __shfl_xor_sync(0xffffffffu, s,  o);
        s2 += __shfl_xor_sync(0xffffffffu, s2, o);
    }
    float mu  = s  * (1.f / 128.f);
    float var = s2 * (1.f / 128.f) - mu * mu;
    float rs  = rsqrtf(var + 1e-5f);
    float* nr = Ns + row * PITCH;
#pragma unroll
    for (int i = 0; i < 16; i++){
        int c = sub + i * 8;
        nr[c] = tf32f((xr[c] - mu) * rs * g[c] + b[c]);
    }
}

// ---------------------------------------------------------------------------
// Windowed attention on the TENSOR pipe.
// Warp w -> head h = w>>1, q-rows s*32..s*32+31 (s = w&1), 2 m16 tiles.
// S = QK^T via MMA; softmax in registers (quad shfl reductions);
// P re-fragmented C->A layout via shfl; O = P V via MMA. O overwrites Qs (fp32).
// Q/K/V are tf32-rounded in smem.
// ---------------------------------------------------------------------------
__device__ __forceinline__ void attention_phase(float* Qs, const float* Ks, const float* Vs, int tid)
{
    const int warp = tid >> 5;
    const int lane = tid & 31;
    const int g = lane >> 2, t = lane & 3;
    const int h = warp >> 1;
    const int s = warp & 1;
    const int co = h * 16;

    const int src0 = (lane & 28) | (t >> 1);   // quad lane holding P col t (as 2t' or 2t'+1)
    const int src1 = src0 + 2;                 // quad lane holding P col t+4
    const bool odd = (t & 1);

#pragma unroll
    for (int mt = 0; mt < 2; mt++){
        const int m0 = s * 32 + mt * 16;

        // ---- S = Q K^T  (m16 x n64, k=16) ----
        float sc[8][4];
#pragma unroll
        for (int nb = 0; nb < 8; nb++){
            sc[nb][0] = sc[nb][1] = sc[nb][2] = sc[nb][3] = 0.f;
        }
#pragma unroll
        for (int k0 = 0; k0 < 16; k0 += 8){
            const float* qp = Qs + (m0 + g) * PITCH + co + k0 + t;
            uint a0 = __float_as_uint(qp[0]);
            uint a1 = __float_as_uint(qp[8 * PITCH]);
            uint a2 = __float_as_uint(qp[4]);
            uint a3 = __float_as_uint(qp[8 * PITCH + 4]);
#pragma unroll
            for (int nb = 0; nb < 8; nb++){
                const float* kp = Ks + (8 * nb + g) * PITCH + co + k0 + t;
                uint b0 = __float_as_uint(kp[0]);
                uint b1 = __float_as_uint(kp[4]);
                mma8(sc[nb], a0, a1, a2, a3, b0, b1);
            }
        }

        // ---- softmax over kv (rows g -> regs 0,1; rows g+8 -> regs 2,3) ----
        float mx0 = -1e30f, mx1 = -1e30f;
#pragma unroll
        for (int nb = 0; nb < 8; nb++){
            mx0 = fmaxf(mx0, fmaxf(sc[nb][0], sc[nb][1]));
            mx1 = fmaxf(mx1, fmaxf(sc[nb][2], sc[nb][3]));
        }
        mx0 = fmaxf(mx0, __shfl_xor_sync(0xffffffffu, mx0, 1));
        mx0 = fmaxf(mx0, __shfl_xor_sync(0xffffffffu, mx0, 2));
        mx1 = fmaxf(mx1, __shfl_xor_sync(0xffffffffu, mx1, 1));
        mx1 = fmaxf(mx1, __shfl_xor_sync(0xffffffffu, mx1, 2));

        float l0 = 0.f, l1 = 0.f;
#pragma unroll
        for (int nb = 0; nb < 8; nb++){
            float p0 = __expf((sc[nb][0] - mx0) * 0.25f);   // softmax(0.25 * s)
            float p1 = __expf((sc[nb][1] - mx0) * 0.25f);
            float p2 = __expf((sc[nb][2] - mx1) * 0.25f);
            float p3 = __expf((sc[nb][3] - mx1) * 0.25f);
            l0 += p0 + p1;  l1 += p2 + p3;
            sc[nb][0] = __uint_as_float(tf32r(p0));
            sc[nb][1] = __uint_as_float(tf32r(p1));
            sc[nb][2] = __uint_as_float(tf32r(p2));
            sc[nb][3] = __uint_as_float(tf32r(p3));
        }
        l0 += __shfl_xor_sync(0xffffffffu, l0, 1);
        l0 += __shfl_xor_sync(0xffffffffu, l0, 2);
        l1 += __shfl_xor_sync(0xffffffffu, l1, 1);
        l1 += __shfl_xor_sync(0xffffffffu, l1, 2);

        // ---- O = P V  (m16 x n16, k=64) ----
        float oc[2][4];
        oc[0][0]=oc[0][1]=oc[0][2]=oc[0][3]=0.f;
        oc[1][0]=oc[1][1]=oc[1][2]=oc[1][3]=0.f;
#pragma unroll
        for (int kb = 0; kb < 8; kb++){
            float p0 = sc[kb][0], p1 = sc[kb][1], p2 = sc[kb][2], p3 = sc[kb][3];
            // re-fragment P (C layout -> A layout) within each quad
            float q00 = __shfl_sync(0xffffffffu, p0, src0);
            float q01 = __shfl_sync(0xffffffffu, p1, src0);
            float q02 = __shfl_sync(0xffffffffu, p0, src1);
            float q03 = __shfl_sync(0xffffffffu, p1, src1);
            float q10 = __shfl_sync(0xffffffffu, p2, src0);
            float q11 = __shfl_sync(0xffffffffu, p3, src0);
            float q12 = __shfl_sync(0xffffffffu, p2, src1);
            float q13 = __shfl_sync(0xffffffffu, p3, src1);
            uint a0 = __float_as_uint(odd ? q01 : q00);   // P[g   ][8kb + t]
            uint a1 = __float_as_uint(odd ? q11 : q10);   // P[g+8 ][8kb + t]
            uint a2 = __float_as_uint(odd ? q03 : q02);   // P[g   ][8kb + t+4]
            uint a3 = __float_as_uint(odd ? q13 : q12);   // P[g+8 ][8kb + t+4]
#pragma unroll
            for (int nb2 = 0; nb2 < 2; nb2++){
                const float* vp = Vs + (8 * kb + t) * PITCH + co + nb2 * 8 + g;
                uint b0 = __float_as_uint(vp[0]);
                uint b1 = __float_as_uint(vp[4 * PITCH]);
                mma8(oc[nb2], a0, a1, a2, a3, b0, b1);
            }
        }
        float i0 = 1.0f / l0, i1 = 1.0f / l1;
#pragma unroll
        for (int nb2 = 0; nb2 < 2; nb2++){
            float* op0 = Qs + (m0 + g) * PITCH + co + nb2 * 8 + 2 * t;
            float* op1 = op0 + 8 * PITCH;
            *(float2*)op0 = make_float2(oc[nb2][0] * i0, oc[nb2][1] * i0);
            *(float2*)op1 = make_float2(oc[nb2][2] * i1, oc[nb2][3] * i1);
        }
    }
}

// ---------------------------------------------------------------------------
// Fused transformer block: one CTA = one 64-token window, tf32 tensor GEMMs.
// ---------------------------------------------------------------------------
extern __shared__ float smbuf[];

__global__ void __launch_bounds__(THREADS, 1)
fused_block_kernel(const float* __restrict__ feats,
                   const float* __restrict__ w_pre,  const float* __restrict__ b_pre,
                   const float* __restrict__ g1,     const float* __restrict__ b1,
                   const float* __restrict__ w_qkv,  const float* __restrict__ b_qkv,
                   const float* __restrict__ w_proj, const float* __restrict__ b_proj,
                   const float* __restrict__ g2,     const float* __restrict__ b2,
                   const float* __restrict__ w_m1,   const float* __restrict__ b_m1,
                   const float* __restrict__ w_m2,   const float* __restrict__ b_m2,
                   const float* __restrict__ w_post, const float* __restrict__ b_post,
                   float* __restrict__ out)
{
    float* Xs = smbuf;                  // residual stream (fp32)     [64][132]
    float* Ns = smbuf + 64 * PITCH;     // LN out / staged feats (tf32-rounded)
    float* Qs = smbuf + 2 * 64 * PITCH; // q -> attention output o
    float* Ks = smbuf + 3 * 64 * PITCH; // k -> MLP hidden (pitch 260 spans Ks+Vs)
    float* Vs = smbuf + 4 * 64 * PITCH; // v
    float* Ws = smbuf + 5 * 64 * PITCH; // weight staging [64][136]
    float* Ts = Ks;

    const int tid  = threadIdx.x;
    const int warp = tid >> 5, lane = tid & 31;
    const int g    = lane >> 2, t = lane & 3;
    const int mg   = warp >> 2, ng = warp & 3;
    const int r0   = mg * 16 + g;
    const size_t tok0 = (size_t)blockIdx.x * 64;

    // stage feats tile [64][64] into Ns cols 0..63 (tf32-rounded)
    for (int i = tid; i < 64 * 16; i += THREADS){
        int tk = i >> 4, c4 = i & 15;
        float4 v = ((const float4*)(feats + (tok0 + tk) * 64))[c4];
        uint4 o = make_uint4(tf32r(v.x), tf32r(v.y), tf32r(v.z), tf32r(v.w));
        *(uint4*)((uint*)Ns + tk * PITCH + c4 * 4) = o;
    }
    // gemm_chunk's internal first __syncthreads orders staging vs compute

    // ---- pre: x2 = feats @ w_pre + b_pre  (K=64 -> N=128) ----
    {
        float c[4][4];
        gemm_chunk<64, 4, 128, false>(Ns, PITCH, w_pre, 128, 0, Ws, tid, c);
#pragma unroll
        for (int nt = 0; nt < 4; nt++){
            int col = ng * 32 + nt * 8 + 2 * t;
            float2 bv = *(const float2*)(b_pre + col);
            *(float2*)(Xs + r0 * PITCH + col)       = make_float2(c[nt][0] + bv.x, c[nt][1] + bv.y);
            *(float2*)(Xs + (r0 + 8) * PITCH + col) = make_float2(c[nt][2] + bv.x, c[nt][3] + bv.y);
        }
    }
    __syncthreads();
    layernorm(Xs, Ns, g1, b1, tid);

    // ---- qkv: 3 col-chunks of w_qkv (N=384), K=128 ----
    {
        float* dsts[3] = {Qs, Ks, Vs};
#pragma unroll
        for (int ch = 0; ch < 3; ch++){
            float c[4][4];
            gemm_chunk<128, 4, 128, false>(Ns, PITCH, w_qkv, 384, ch * 128, Ws, tid, c);
            float* dst = dsts[ch];
#pragma unroll
            for (int nt = 0; nt < 4; nt++){
                int col = ng * 32 + nt * 8 + 2 * t;
                float2 bv = *(const float2*)(b_qkv + ch * 128 + col);
                *(float2*)(dst + r0 * PITCH + col) =
                    make_float2(tf32f(c[nt][0] + bv.x), tf32f(c[nt][1] + bv.y));
                *(float2*)(dst + (r0 + 8) * PITCH + col) =
                    make_float2(tf32f(c[nt][2] + bv.x), tf32f(c[nt][3] + bv.y));
            }
        }
    }
    __syncthreads();

    attention_phase(Qs, Ks, Vs, tid);   // o -> Qs (fp32), tensor-pipe MMA
    __syncthreads();

    // ---- proj + residual: x2 += o @ w_proj + b_proj ----
    {
        float c[4][4];
        gemm_chunk<128, 4, 128, true>(Qs, PITCH, w_proj, 128, 0, Ws, tid, c);
#pragma unroll
        for (int nt = 0; nt < 4; nt++){
            int col = ng * 32 + nt * 8 + 2 * t;
            float2 bv = *(const float2*)(b_proj + col);
            float2* p0 = (float2*)(Xs + r0 * PITCH + col);
            float2* p1 = (float2*)(Xs + (r0 + 8) * PITCH + col);
            float2 v0 = *p0, v1 = *p1;
            v0.x += c[nt][0] + bv.x; v0.y += c[nt][1] + bv.y;
            v1.x += c[nt][2] + bv.x; v1.y += c[nt][3] + bv.y;
            *p0 = v0; *p1 = v1;
        }
    }
    __syncthreads();
    layernorm(Xs, Ns, g2, b2, tid);

    // ---- mlp1: t = gelu(n2 @ w_m1 + b_m1)  (N=256: 2 col-chunks) ----
#pragma unroll
    for (int ch = 0; ch < 2; ch++){
        float c[4][4];
        gemm_chunk<128, 4, 128, false>(Ns, PITCH, w_m1, 256, ch * 128, Ws, tid, c);
#pragma unroll
        for (int nt = 0; nt < 4; nt++){
            int col = ng * 32 + nt * 8 + 2 * t;
            float2 bv = *(const float2*)(b_m1 + ch * 128 + col);
            float v[4] = {c[nt][0] + bv.x, c[nt][1] + bv.y,
                          c[nt][2] + bv.x, c[nt][3] + bv.y};
#pragma unroll
            for (int i = 0; i < 4; i++)
                v[i] = tf32f(0.5f * v[i] * (1.0f + erff(v[i] * 0.70710678118654752f)));
            *(float2*)(Ts + r0 * TPITCH + ch * 128 + col)       = make_float2(v[0], v[1]);
            *(float2*)(Ts + (r0 + 8) * TPITCH + ch * 128 + col) = make_float2(v[2], v[3]);
        }
    }

    // ---- mlp2 + residual: x2 += t @ w_m2 + b_m2  (K=256) ----
    {
        float c[4][4];
        gemm_chunk<256, 4, 128, false>(Ts, TPITCH, w_m2, 128, 0, Ws, tid, c);
#pragma unroll
        for (int nt = 0; nt < 4; nt++){
            int col = ng * 32 + nt * 8 + 2 * t;
            float2 bv = *(const float2*)(b_m2 + col);
            float2* p0 = (float2*)(Xs + r0 * PITCH + col);
            float2* p1 = (float2*)(Xs + (r0 + 8) * PITCH + col);
            float2 v0 = *p0, v1 = *p1;
            v0.x += c[nt][0] + bv.x; v0.y += c[nt][1] + bv.y;
            v1.x += c[nt][2] + bv.x; v1.y += c[nt][3] + bv.y;
            *p0 = v0; *p1 = v1;
        }
    }

    // ---- post: out = x2 @ w_post + b_post  (N=64, NT=2) ----
    {
        float c[2][4];
        gemm_chunk<128, 2, 64, true>(Xs, PITCH, w_post, 64, 0, Ws, tid, c);
#pragma unroll
        for (int nt = 0; nt < 2; nt++){
            int col = ng * 16 + nt * 8 + 2 * t;
            float2 bv = *(const float2*)(b_post + col);
            *(float2*)(out + (tok0 + r0) * 64 + col) =
                make_float2(c[nt][0] + bv.x, c[nt][1] + bv.y);
            *(float2*)(out + (tok0 + r0 + 8) * 64 + col) =
                make_float2(c[nt][2] + bv.x, c[nt][3] + bv.y);
        }
    }
}

extern "C" void kernel_launch(void* const* d_in, const int* in_sizes, int n_in,
                              void* d_out, int out_size)
{
    const float* feats  = (const float*)d_in[0];
    const float* w_pre  = (const float*)d_in[1];
    const float* b_pre  = (const float*)d_in[2];
    const float* g1     = (const float*)d_in[3];
    const float* b1     = (const float*)d_in[4];
    const float* w_qkv  = (const float*)d_in[5];
    const float* b_qkv  = (const float*)d_in[6];
    const float* w_proj = (const float*)d_in[7];
    const float* b_proj = (const float*)d_in[8];
    const float* g2     = (const float*)d_in[9];
    const float* b2     = (const float*)d_in[10];
    const float* w_m1   = (const float*)d_in[11];
    const float* b_m1   = (const float*)d_in[12];
    const float* w_m2   = (const float*)d_in[13];
    const float* b_m2   = (const float*)d_in[14];
    const float* w_post = (const float*)d_in[15];
    const float* b_post = (const float*)d_in[16];
    float* out = (float*)d_out;

    const int ntok    = in_sizes[0] / 64;   // C = 64
    const int nblocks = ntok / 64;          // PS = 64 tokens per window
    const size_t smem = (size_t)(5 * 64 * PITCH + 64 * WPITCH) * sizeof(float); // 203776 B

    cudaFuncSetAttribute(fused_block_kernel,
                         cudaFuncAttributeMaxDynamicSharedMemorySize, (int)smem);

    fused_block_kernel<<<nblocks, THREADS, smem>>>(feats, w_pre, b_pre, g1, b1,
                                                   w_qkv, b_qkv, w_proj, b_proj,
                                                   g2, b2, w_m1, b_m1, w_m2, b_m2,
                                                   w_post, b_post, out);
}